// round 15
// baseline (speedup 1.0000x reference)
#include <cuda_runtime.h>
#include <cuda_fp16.h>
#include <math.h>
#include <stdint.h>

#define Bn   16
#define Sn   512
#define Dn   2048
#define Hn   16
#define HDn  128
#define Mtot (Bn*Sn)      // 8192
#define NQKV (3 * Dn)     // 6144

// ---------------- scratch (alloc-free: __device__ globals) ----------------
__device__ __half g_x16[(size_t)Mtot * Dn];
__device__ __half g_o16[(size_t)Mtot * Dn];
__device__ __half g_wqkv[(size_t)Dn * NQKV];   // [k][n'] n'=6144
__device__ __half g_wo16[(size_t)Dn * Dn];     // [k][n]
__device__ __half g_q16[(size_t)Mtot * Dn];
__device__ __half g_k16[(size_t)Mtot * Dn];
__device__ __half g_v16[(size_t)Mtot * Dn];

// ============================================================================
// PTX helpers
// ============================================================================
__device__ __forceinline__ uint32_t smem_u32(const void* p) {
    uint32_t a;
    asm("{ .reg .u64 t; cvta.to.shared.u64 t, %1; cvt.u32.u64 %0, t; }" : "=r"(a) : "l"(p));
    return a;
}
__device__ __forceinline__ void cp16(uint32_t saddr, const void* gptr) {
    asm volatile("cp.async.cg.shared.global [%0], [%1], 16;" :: "r"(saddr), "l"(gptr) : "memory");
}
__device__ __forceinline__ void cp_commit() {
    asm volatile("cp.async.commit_group;" ::: "memory");
}
template <int N>
__device__ __forceinline__ void cp_wait() {
    asm volatile("cp.async.wait_group %0;" :: "n"(N) : "memory");
}
__device__ __forceinline__ void ldsm4(uint32_t* r, uint32_t addr) {
    asm volatile("ldmatrix.sync.aligned.m8n8.x4.shared.b16 {%0,%1,%2,%3}, [%4];"
                 : "=r"(r[0]), "=r"(r[1]), "=r"(r[2]), "=r"(r[3]) : "r"(addr));
}
__device__ __forceinline__ void ldsm4t(uint32_t* r, uint32_t addr) {
    asm volatile("ldmatrix.sync.aligned.m8n8.x4.trans.shared.b16 {%0,%1,%2,%3}, [%4];"
                 : "=r"(r[0]), "=r"(r[1]), "=r"(r[2]), "=r"(r[3]) : "r"(addr));
}
__device__ __forceinline__ void mma_f16(float* d, const uint32_t* a, const uint32_t* b) {
    asm volatile("mma.sync.aligned.m16n8k16.row.col.f32.f16.f16.f32 "
                 "{%0,%1,%2,%3}, {%4,%5,%6,%7}, {%8,%9}, {%0,%1,%2,%3};"
                 : "+f"(d[0]), "+f"(d[1]), "+f"(d[2]), "+f"(d[3])
                 : "r"(a[0]), "r"(a[1]), "r"(a[2]), "r"(a[3]), "r"(b[0]), "r"(b[1]));
}
// fp16-accumulator variant: 2x HMMA throughput, D/C are 2 packed-half regs
__device__ __forceinline__ void mma_h16(uint32_t* d, const uint32_t* a, const uint32_t* b) {
    asm volatile("mma.sync.aligned.m16n8k16.row.col.f16.f16.f16.f16 "
                 "{%0,%1}, {%2,%3,%4,%5}, {%6,%7}, {%0,%1};"
                 : "+r"(d[0]), "+r"(d[1])
                 : "r"(a[0]), "r"(a[1]), "r"(a[2]), "r"(a[3]), "r"(b[0]), "r"(b[1]));
}
__device__ __forceinline__ uint32_t pack_h2(float a, float b) {
    __half2 h = __floats2half2_rn(a, b);
    return *reinterpret_cast<uint32_t*>(&h);
}

// ============================================================================
// Tile geometry
// ============================================================================
#define KC      32
#define ROWB    80
#define TILE_B  (128 * ROWB)         // 10240 B
#define VROWB   272
#define WTILE_B (32 * VROWB)         // 8704 B

template <typename T>
__device__ __forceinline__ void load_tile(const T* __restrict__ g,
                                          int ldg, uint32_t sdst, int tid)
{
    #pragma unroll
    for (int it = 0; it < 2; ++it) {
        int idx = tid + it * 256;
        int row = idx >> 2, seg = idx & 3;
        cp16(sdst + (uint32_t)(row * ROWB + seg * 16),
             (const char*)(g + (size_t)row * ldg) + seg * 16);
    }
}
__device__ __forceinline__ void load_wtile(const __half* __restrict__ g,
                                           int ldg, uint32_t sdst, int tid)
{
    #pragma unroll
    for (int it = 0; it < 2; ++it) {
        int idx = tid + it * 256;
        int row = idx >> 4, seg = idx & 15;
        cp16(sdst + (uint32_t)(row * VROWB + seg * 16),
             (const char*)(g + (size_t)row * ldg) + seg * 16);
    }
}
__device__ __forceinline__ void load_tile128w(const __half* __restrict__ g,
                                              uint32_t sdst, int tid)
{
    #pragma unroll
    for (int it = 0; it < 8; ++it) {
        int idx = tid + it * 256;
        int row = idx >> 4, seg = idx & 15;
        cp16(sdst + (uint32_t)(row * VROWB + seg * 16),
             (const char*)(g + (size_t)row * Dn) + seg * 16);
    }
}

// ============================================================================
// Preprocessing
// ============================================================================
__global__ void __launch_bounds__(256)
half_kernel(const float4* __restrict__ X, __half* __restrict__ H)
{
    size_t i = (size_t)blockIdx.x * 256 + threadIdx.x;
    float4 v = X[i];
    __half2* H2 = (__half2*)H;
    H2[2*i]   = __floats2half2_rn(v.x, v.y);
    H2[2*i+1] = __floats2half2_rn(v.z, v.w);
}

__global__ void __launch_bounds__(256)
convW3_kernel(const float4* __restrict__ Wq, const float4* __restrict__ Wk,
              const float4* __restrict__ Wv, __half* __restrict__ Out)
{
    const size_t QUARTER = (size_t)Dn * Dn / 4;
    size_t idx = (size_t)blockIdx.x * 256 + threadIdx.x;
    int which = (int)(idx / QUARTER);
    size_t rem = idx - (size_t)which * QUARTER;
    size_t k   = rem / (Dn / 4);
    size_t seg = rem - k * (Dn / 4);
    const float4* src = (which == 0) ? Wq : (which == 1) ? Wk : Wv;
    float4 v = src[k * (Dn / 4) + seg];
    __half2* dst = (__half2*)&Out[k * NQKV + (size_t)which * Dn + seg * 4];
    dst[0] = __floats2half2_rn(v.x, v.y);
    dst[1] = __floats2half2_rn(v.z, v.w);
}

__global__ void __launch_bounds__(256)
convW_kernel(const float4* __restrict__ W, __half* __restrict__ Out)
{
    size_t i = (size_t)blockIdx.x * 256 + threadIdx.x;
    float4 v = W[i];
    __half2* dst = (__half2*)&Out[i * 4];
    dst[0] = __floats2half2_rn(v.x, v.y);
    dst[1] = __floats2half2_rn(v.z, v.w);
}

// ============================================================================
// NT GEMM. EPI 0: WO (fp32-acc, fp32 out). EPI 1: merged QKV (fp16-acc with
// fp32 promotion per K=32 chunk; 2x HMMA rate), per-slab bias/RoPE, fp16 out.
// ============================================================================
#define NTBUF_B      (TILE_B + WTILE_B)   // 18944
#define GEMM_SMEM_NT (2 * NTBUF_B)        // 37888

template <int EPI>
__global__ void __launch_bounds__(256)
gemm_nt(const __half* __restrict__ A, const __half* __restrict__ W, int ldw,
        const float* __restrict__ b0, const float* __restrict__ b1,
        const float* __restrict__ b2,
        __half* __restrict__ o0, __half* __restrict__ o1,
        __half* __restrict__ o2, float* __restrict__ Cf)
{
    extern __shared__ char smem_raw[];
    const uint32_t sb = smem_u32(smem_raw);

    const int tid  = threadIdx.x;
    const int wid  = tid >> 5;
    const int lane = tid & 31;
    const int rowStart = blockIdx.y * 128;
    const int colStart = blockIdx.x * 128;
    const int which = colStart >> 11;
    const int ccol  = colStart & (Dn - 1);
    const int warp_m = (wid & 1) * 64;
    const int warp_n = (wid >> 1) * 32;

    const float* bias = (EPI == 0) ? b0 : (which == 0) ? b0 : (which == 1) ? b1 : b2;
    __half* OH = (which == 0) ? o0 : (which == 1) ? o1 : o2;
    const bool rope = (EPI == 1) && (which < 2);

    const __half* gA = A + (size_t)rowStart * Dn;
    const __half* gW = W + colStart;

    const uint32_t aoff  = (uint32_t)((lane & 15) * ROWB + (lane >> 4) * 16);
    const uint32_t boffT = (uint32_t)(((lane & 7) + ((lane >> 3) & 1) * 8) * VROWB
                                      + (lane >> 4) * 16);

    float acc[4][4][4];
    #pragma unroll
    for (int i = 0; i < 4; i++)
        #pragma unroll
        for (int j = 0; j < 4; j++)
            #pragma unroll
            for (int r = 0; r < 4; r++) acc[i][j][r] = 0.f;

    const int NCHUNK = Dn / KC;   // 64

    {
        const uint32_t bb = sb;
        load_tile (gA, Dn, bb, tid);
        load_wtile(gW, ldw, bb + TILE_B, tid);
        cp_commit();
    }

    #pragma unroll 1
    for (int c = 0; c < NCHUNK; ++c) {
        if (c + 1 < NCHUNK) {
            const uint32_t bb = sb + ((c + 1) & 1) * NTBUF_B;
            const int k0 = (c + 1) * KC;
            load_tile (gA + k0, Dn, bb, tid);
            load_wtile(gW + (size_t)k0 * ldw, ldw, bb + TILE_B, tid);
            cp_commit();
            cp_wait<1>();
        } else {
            cp_wait<0>();
        }
        __syncthreads();

        const uint32_t bb = sb + (c & 1) * NTBUF_B;
        const uint32_t sA = bb, sW = bb + TILE_B;

        if (EPI == 1) {
            // ---- fp16-acc chunk (K=32, 2 roundings), then fp32 promote ----
            uint32_t hacc[4][4][2];
            #pragma unroll
            for (int i = 0; i < 4; ++i)
                #pragma unroll
                for (int j = 0; j < 4; ++j) { hacc[i][j][0] = 0u; hacc[i][j][1] = 0u; }

            #pragma unroll
            for (int kk = 0; kk < 2; ++kk) {
                const uint32_t kbA = (uint32_t)(kk * 32);
                const uint32_t kbB = (uint32_t)(kk * 16 * VROWB);
                uint32_t afrag[4][4], bfrag[4][2];

                #pragma unroll
                for (int i = 0; i < 4; ++i)
                    ldsm4(afrag[i], sA + aoff + kbA + (uint32_t)((warp_m + i*16) * ROWB));
                #pragma unroll
                for (int g = 0; g < 2; ++g) {
                    uint32_t r[4];
                    ldsm4t(r, sW + boffT + kbB + (uint32_t)((warp_n + g*16) * 2));
                    bfrag[g*2][0] = r[0]; bfrag[g*2][1] = r[1];
                    bfrag[g*2+1][0] = r[2]; bfrag[g*2+1][1] = r[3];
                }
                #pragma unroll
                for (int i = 0; i < 4; ++i)
                    #pragma unroll
                    for (int j = 0; j < 4; ++j)
                        mma_h16(hacc[i][j], afrag[i], bfrag[j]);
            }
            // promote to fp32 master
            #pragma unroll
            for (int i = 0; i < 4; ++i)
                #pragma unroll
                for (int j = 0; j < 4; ++j) {
                    float2 p0 = __half22float2(*(__half2*)&hacc[i][j][0]);
                    float2 p1 = __half22float2(*(__half2*)&hacc[i][j][1]);
                    acc[i][j][0] += p0.x; acc[i][j][1] += p0.y;
                    acc[i][j][2] += p1.x; acc[i][j][3] += p1.y;
                }
        } else {
            // ---- fp32-acc path (WO) ----
            #pragma unroll
            for (int kk = 0; kk < 2; ++kk) {
                const uint32_t kbA = (uint32_t)(kk * 32);
                const uint32_t kbB = (uint32_t)(kk * 16 * VROWB);
                uint32_t afrag[4][4], bfrag[4][2];

                #pragma unroll
                for (int i = 0; i < 4; ++i)
                    ldsm4(afrag[i], sA + aoff + kbA + (uint32_t)((warp_m + i*16) * ROWB));
                #pragma unroll
                for (int g = 0; g < 2; ++g) {
                    uint32_t r[4];
                    ldsm4t(r, sW + boffT + kbB + (uint32_t)((warp_n + g*16) * 2));
                    bfrag[g*2][0] = r[0]; bfrag[g*2][1] = r[1];
                    bfrag[g*2+1][0] = r[2]; bfrag[g*2+1][1] = r[3];
                }
                #pragma unroll
                for (int i = 0; i < 4; ++i)
                    #pragma unroll
                    for (int j = 0; j < 4; ++j)
                        mma_f16(acc[i][j], afrag[i], bfrag[j]);
            }
        }
        __syncthreads();
    }

    #pragma unroll
    for (int i = 0; i < 4; ++i) {
        const int r0 = rowStart + warp_m + i * 16 + (lane >> 2);
        #pragma unroll
        for (int half = 0; half < 2; ++half) {
            const int r = r0 + half * 8;
            const int s = r & (Sn - 1);
            #pragma unroll
            for (int j = 0; j < 4; ++j) {
                const int c0 = ccol + warp_n + j * 8 + (lane & 3) * 2;
                float v0 = acc[i][j][half*2]   + bias[c0];
                float v1 = acc[i][j][half*2+1] + bias[c0 + 1];
                if (rope) {
                    int pidx = (c0 & (HDn - 1)) >> 1;
                    float inv = exp2f((float)pidx * (-13.287712379549449f / 64.0f));
                    float sn, cs;
                    sincosf((float)s * inv, &sn, &cs);
                    float e = v0, o = v1;
                    v0 = e * cs - o * sn;
                    v1 = o * cs + e * sn;
                }
                if (EPI == 0)
                    *(float2*)&Cf[(size_t)r * Dn + c0] = make_float2(v0, v1);
                else
                    *(__half2*)&OH[(size_t)r * Dn + c0] = __floats2half2_rn(v0, v1);
            }
        }
    }
}

// ============================================================================
// Flash-fused attention (unchanged from R13/R14)
// ============================================================================
#define QSZ        (128 * VROWB)
#define KVSZ       (2 * QSZ)
#define FLASH_SMEM (QSZ + 2 * KVSZ)        // 174080

__global__ void __launch_bounds__(256)
flash_f16(const __half* __restrict__ Q, const __half* __restrict__ K,
          const __half* __restrict__ V, __half* __restrict__ O16)
{
    extern __shared__ char smem_raw[];
    const uint32_t sb = smem_u32(smem_raw);

    const int rb = blockIdx.x;
    const int bh = blockIdx.y;
    const int b  = bh >> 4, h = bh & 15;
    const int tid  = threadIdx.x;
    const int wid  = tid >> 5;
    const int lane = tid & 31;

    const size_t headoff = (size_t)(b * Sn) * Dn + h * HDn;
    const __half* gQ = Q + headoff + (size_t)(rb * 128) * Dn;
    const __half* gK = K + headoff;
    const __half* gV = V + headoff;

    const uint32_t sQ = sb;
    const uint32_t aoffV  = (uint32_t)((lane & 15) * VROWB + (lane >> 4) * 16);
    const uint32_t boffV  = (uint32_t)(((lane & 7) + ((lane >> 4) << 3)) * VROWB
                                       + ((lane >> 3) & 1) * 16);
    const uint32_t boffTV = (uint32_t)(((lane & 7) + ((lane >> 3) & 1) * 8) * VROWB
                                       + (lane >> 4) * 16);

    float oacc[16][4];
    #pragma unroll
    for (int j = 0; j < 16; ++j)
        #pragma unroll
        for (int r = 0; r < 4; ++r) oacc[j][r] = 0.f;
    float m[2] = {-1e30f, -1e30f};
    float l[2] = {0.f, 0.f};

    load_tile128w(gQ, sQ, tid);
    load_tile128w(gK, sb + QSZ, tid);
    load_tile128w(gV, sb + QSZ + QSZ, tid);
    cp_commit();

    const float scale = 0.08838834764831843f;
    const uint32_t aQ = sQ + (uint32_t)(wid * 16) * VROWB + aoffV;

    #pragma unroll 1
    for (int kb = 0; kb <= rb; ++kb) {
        if (kb < rb) {
            const uint32_t bb = sb + QSZ + ((kb + 1) & 1) * KVSZ;
            load_tile128w(gK + (size_t)((kb + 1) * 128) * Dn, bb, tid);
            load_tile128w(gV + (size_t)((kb + 1) * 128) * Dn, bb + QSZ, tid);
            cp_commit();
            cp_wait<1>();
        } else {
            cp_wait<0>();
        }
        __syncthreads();

        const uint32_t kvb = sb + QSZ + (kb & 1) * KVSZ;
        const uint32_t sK = kvb, sV = kvb + QSZ;

        float sacc[16][4];
        #pragma unroll
        for (int j = 0; j < 16; ++j)
            #pragma unroll
            for (int r = 0; r < 4; ++r) sacc[j][r] = 0.f;

        #pragma unroll
        for (int kd = 0; kd < 8; ++kd) {
            uint32_t af[4];
            ldsm4(af, aQ + (uint32_t)(kd * 32));
            #pragma unroll
            for (int p = 0; p < 8; ++p) {
                uint32_t r[4];
                ldsm4(r, sK + (uint32_t)(p * 16) * VROWB + boffV + (uint32_t)(kd * 32));
                uint32_t b0[2] = {r[0], r[1]}, b1[2] = {r[2], r[3]};
                mma_f16(sacc[2*p],     af, b0);
                mma_f16(sacc[2*p + 1], af, b1);
            }
        }

        const bool diag = (kb == rb);
        #pragma unroll
        for (int j = 0; j < 16; ++j)
            #pragma unroll
            for (int r = 0; r < 4; ++r) {
                float v = sacc[j][r] * scale;
                if (diag) {
                    int t_loc = j * 8 + (lane & 3) * 2 + (r & 1);
                    int s_loc = wid * 16 + (lane >> 2) + ((r >> 1) & 1) * 8;
                    if (t_loc > s_loc) v = -1e30f;
                }
                sacc[j][r] = v;
            }

        float bm[2] = {-1e30f, -1e30f};
        #pragma unroll
        for (int j = 0; j < 16; ++j) {
            bm[0] = fmaxf(bm[0], fmaxf(sacc[j][0], sacc[j][1]));
            bm[1] = fmaxf(bm[1], fmaxf(sacc[j][2], sacc[j][3]));
        }
        #pragma unroll
        for (int o = 1; o <= 2; o <<= 1) {
            bm[0] = fmaxf(bm[0], __shfl_xor_sync(0xffffffffu, bm[0], o));
            bm[1] = fmaxf(bm[1], __shfl_xor_sync(0xffffffffu, bm[1], o));
        }
        float mn[2], f[2];
        #pragma unroll
        for (int hh = 0; hh < 2; ++hh) {
            mn[hh] = fmaxf(m[hh], bm[hh]);
            f[hh]  = __expf(m[hh] - mn[hh]);
            m[hh]  = mn[hh];
        }

        float rs[2] = {0.f, 0.f};
        #pragma unroll
        for (int j = 0; j < 16; ++j) {
            #pragma unroll
            for (int r = 0; r < 4; ++r) {
                const int hh = r >> 1;
                float e = __expf(sacc[j][r] - mn[hh]);
                sacc[j][r] = e;
                rs[hh] += e;
            }
        }
        #pragma unroll
        for (int o = 1; o <= 2; o <<= 1) {
            rs[0] += __shfl_xor_sync(0xffffffffu, rs[0], o);
            rs[1] += __shfl_xor_sync(0xffffffffu, rs[1], o);
        }
        l[0] = l[0] * f[0] + rs[0];
        l[1] = l[1] * f[1] + rs[1];

        #pragma unroll
        for (int j = 0; j < 16; ++j) {
            oacc[j][0] *= f[0]; oacc[j][1] *= f[0];
            oacc[j][2] *= f[1]; oacc[j][3] *= f[1];
        }

        #pragma unroll
        for (int kt = 0; kt < 8; ++kt) {
            uint32_t pk[4];
            pk[0] = pack_h2(sacc[2*kt][0],     sacc[2*kt][1]);
            pk[1] = pack_h2(sacc[2*kt][2],     sacc[2*kt][3]);
            pk[2] = pack_h2(sacc[2*kt + 1][0], sacc[2*kt + 1][1]);
            pk[3] = pack_h2(sacc[2*kt + 1][2], sacc[2*kt + 1][3]);
            #pragma unroll
            for (int g = 0; g < 8; ++g) {
                uint32_t r[4];
                ldsm4t(r, sV + (uint32_t)(kt * 16) * VROWB + boffTV + (uint32_t)(g * 32));
                uint32_t b0[2] = {r[0], r[1]}, b1[2] = {r[2], r[3]};
                mma_f16(oacc[2*g],     pk, b0);
                mma_f16(oacc[2*g + 1], pk, b1);
            }
        }
        __syncthreads();
    }

    const float inv0 = 1.f / l[0], inv1 = 1.f / l[1];
    #pragma unroll
    for (int hh = 0; hh < 2; ++hh) {
        const int s = rb * 128 + wid * 16 + (lane >> 2) + hh * 8;
        const size_t rbase = ((size_t)(b * Sn + s)) * Dn + h * HDn;
        const float inv = hh ? inv1 : inv0;
        #pragma unroll
        for (int j = 0; j < 16; ++j) {
            const int d = j * 8 + (lane & 3) * 2;
            *(__half2*)&O16[rbase + d] =
                __floats2half2_rn(oacc[j][hh*2] * inv, oacc[j][hh*2 + 1] * inv);
        }
    }
}

// ============================================================================
extern "C" void kernel_launch(void* const* d_in, const int* in_sizes, int n_in,
                              void* d_out, int out_size)
{
    const float* x  = (const float*)d_in[0];
    const float* wq = (const float*)d_in[2];
    const float* bq = (const float*)d_in[3];
    const float* wk = (const float*)d_in[4];
    const float* bk = (const float*)d_in[5];
    const float* wv = (const float*)d_in[6];
    const float* bv = (const float*)d_in[7];
    const float* wo = (const float*)d_in[8];
    const float* bo = (const float*)d_in[9];
    float* out = (float*)d_out;

    __half *x16, *o16, *wqkv, *wo16, *q16, *k16, *v16;
    cudaGetSymbolAddress((void**)&x16,  g_x16);
    cudaGetSymbolAddress((void**)&o16,  g_o16);
    cudaGetSymbolAddress((void**)&wqkv, g_wqkv);
    cudaGetSymbolAddress((void**)&wo16, g_wo16);
    cudaGetSymbolAddress((void**)&q16,  g_q16);
    cudaGetSymbolAddress((void**)&k16,  g_k16);
    cudaGetSymbolAddress((void**)&v16,  g_v16);

    cudaFuncSetAttribute(gemm_nt<0>, cudaFuncAttributeMaxDynamicSharedMemorySize, GEMM_SMEM_NT);
    cudaFuncSetAttribute(gemm_nt<1>, cudaFuncAttributeMaxDynamicSharedMemorySize, GEMM_SMEM_NT);
    cudaFuncSetAttribute(flash_f16,  cudaFuncAttributeMaxDynamicSharedMemorySize, FLASH_SMEM);

    const int nXBlks  = (int)(((size_t)Mtot * Dn / 4) / 256);
    const int nW3Blks = (int)(((size_t)3 * Dn * Dn / 4) / 256);
    const int nW1Blks = (int)(((size_t)Dn * Dn / 4) / 256);

    // --- preprocessing ---
    half_kernel<<<nXBlks, 256>>>((const float4*)x, x16);
    convW3_kernel<<<nW3Blks, 256>>>((const float4*)wq, (const float4*)wk,
                                    (const float4*)wv, wqkv);
    convW_kernel<<<nW1Blks, 256>>>((const float4*)wo, wo16);

    // --- merged QKV projection (fp16-acc + chunked fp32 promote) ---
    dim3 gQKV(NQKV / 128, Mtot / 128);
    gemm_nt<1><<<gQKV, 256, GEMM_SMEM_NT>>>(x16, wqkv, NQKV,
                                            bq, bk, bv, q16, k16, v16, nullptr);

    // --- flash-fused attention ---
    dim3 gF(Sn / 128, Bn * Hn);
    flash_f16<<<gF, 256, FLASH_SMEM>>>(q16, k16, v16, o16);

    // --- output projection (fp32-acc) ---
    dim3 gWO(Dn / 128, Mtot / 128);
    gemm_nt<0><<<gWO, 256, GEMM_SMEM_NT>>>(o16, wo16, Dn,
                                           bo, nullptr, nullptr,
                                           nullptr, nullptr, nullptr, out);
}

// round 16
// speedup vs baseline: 1.4655x; 1.4655x over previous
#include <cuda_runtime.h>
#include <cuda_fp16.h>
#include <math.h>
#include <stdint.h>

#define Bn   16
#define Sn   512
#define Dn   2048
#define Hn   16
#define HDn  128
#define Mtot (Bn*Sn)      // 8192
#define NQKV (3 * Dn)     // 6144

// ---------------- scratch (alloc-free: __device__ globals) ----------------
__device__ __half g_x16[(size_t)Mtot * Dn];
__device__ __half g_o16[(size_t)Mtot * Dn];
__device__ __half g_wqkv[(size_t)Dn * NQKV];   // [k][n'] n'=6144
__device__ __half g_wo16[(size_t)Dn * Dn];     // [k][n]
__device__ __half g_q16[(size_t)Mtot * Dn];
__device__ __half g_k16[(size_t)Mtot * Dn];
__device__ __half g_v16[(size_t)Mtot * Dn];

// ============================================================================
// PTX helpers
// ============================================================================
__device__ __forceinline__ uint32_t smem_u32(const void* p) {
    uint32_t a;
    asm("{ .reg .u64 t; cvta.to.shared.u64 t, %1; cvt.u32.u64 %0, t; }" : "=r"(a) : "l"(p));
    return a;
}
__device__ __forceinline__ void cp16(uint32_t saddr, const void* gptr) {
    asm volatile("cp.async.cg.shared.global [%0], [%1], 16;" :: "r"(saddr), "l"(gptr) : "memory");
}
__device__ __forceinline__ void cp_commit() {
    asm volatile("cp.async.commit_group;" ::: "memory");
}
template <int N>
__device__ __forceinline__ void cp_wait() {
    asm volatile("cp.async.wait_group %0;" :: "n"(N) : "memory");
}
__device__ __forceinline__ void ldsm4(uint32_t* r, uint32_t addr) {
    asm volatile("ldmatrix.sync.aligned.m8n8.x4.shared.b16 {%0,%1,%2,%3}, [%4];"
                 : "=r"(r[0]), "=r"(r[1]), "=r"(r[2]), "=r"(r[3]) : "r"(addr));
}
__device__ __forceinline__ void ldsm4t(uint32_t* r, uint32_t addr) {
    asm volatile("ldmatrix.sync.aligned.m8n8.x4.trans.shared.b16 {%0,%1,%2,%3}, [%4];"
                 : "=r"(r[0]), "=r"(r[1]), "=r"(r[2]), "=r"(r[3]) : "r"(addr));
}
__device__ __forceinline__ void mma_f16(float* d, const uint32_t* a, const uint32_t* b) {
    asm volatile("mma.sync.aligned.m16n8k16.row.col.f32.f16.f16.f32 "
                 "{%0,%1,%2,%3}, {%4,%5,%6,%7}, {%8,%9}, {%0,%1,%2,%3};"
                 : "+f"(d[0]), "+f"(d[1]), "+f"(d[2]), "+f"(d[3])
                 : "r"(a[0]), "r"(a[1]), "r"(a[2]), "r"(a[3]), "r"(b[0]), "r"(b[1]));
}
__device__ __forceinline__ uint32_t pack_h2(float a, float b) {
    __half2 h = __floats2half2_rn(a, b);
    return *reinterpret_cast<uint32_t*>(&h);
}

// ============================================================================
// Tile geometry
// ============================================================================
#define KC      32
#define ROWB    80
#define TILE_B  (128 * ROWB)         // 10240 B
#define VROWB   272
#define WTILE_B (32 * VROWB)         // 8704 B

template <typename T>
__device__ __forceinline__ void load_tile(const T* __restrict__ g,
                                          int ldg, uint32_t sdst, int tid)
{
    #pragma unroll
    for (int it = 0; it < 2; ++it) {
        int idx = tid + it * 256;
        int row = idx >> 2, seg = idx & 3;
        cp16(sdst + (uint32_t)(row * ROWB + seg * 16),
             (const char*)(g + (size_t)row * ldg) + seg * 16);
    }
}
__device__ __forceinline__ void load_wtile(const __half* __restrict__ g,
                                           int ldg, uint32_t sdst, int tid)
{
    #pragma unroll
    for (int it = 0; it < 2; ++it) {
        int idx = tid + it * 256;
        int row = idx >> 4, seg = idx & 15;
        cp16(sdst + (uint32_t)(row * VROWB + seg * 16),
             (const char*)(g + (size_t)row * ldg) + seg * 16);
    }
}
__device__ __forceinline__ void load_tile128w(const __half* __restrict__ g,
                                              uint32_t sdst, int tid)
{
    #pragma unroll
    for (int it = 0; it < 8; ++it) {
        int idx = tid + it * 256;
        int row = idx >> 4, seg = idx & 15;
        cp16(sdst + (uint32_t)(row * VROWB + seg * 16),
             (const char*)(g + (size_t)row * Dn) + seg * 16);
    }
}

// ============================================================================
// Preprocessing: x fp32->fp16; all 4 W matrices converted in ONE launch
// ============================================================================
__global__ void __launch_bounds__(256)
half_kernel(const float4* __restrict__ X, __half* __restrict__ H)
{
    size_t i = (size_t)blockIdx.x * 256 + threadIdx.x;
    float4 v = X[i];
    __half2* H2 = (__half2*)H;
    H2[2*i]   = __floats2half2_rn(v.x, v.y);
    H2[2*i+1] = __floats2half2_rn(v.z, v.w);
}

// q|k|v -> wqkv [k][which*2048 + n]; o -> wo16 linear
__global__ void __launch_bounds__(256)
convW4_kernel(const float4* __restrict__ Wq, const float4* __restrict__ Wk,
              const float4* __restrict__ Wv, const float4* __restrict__ Wo,
              __half* __restrict__ OutQKV, __half* __restrict__ OutO)
{
    const size_t QUARTER = (size_t)Dn * Dn / 4;    // float4 count per matrix
    size_t idx = (size_t)blockIdx.x * 256 + threadIdx.x;   // 0 .. 4*QUARTER-1
    int which = (int)(idx / QUARTER);
    size_t rem = idx - (size_t)which * QUARTER;

    if (which == 3) {
        float4 v = Wo[rem];
        __half2* dst = (__half2*)&OutO[rem * 4];
        dst[0] = __floats2half2_rn(v.x, v.y);
        dst[1] = __floats2half2_rn(v.z, v.w);
        return;
    }
    size_t k   = rem / (Dn / 4);
    size_t seg = rem - k * (Dn / 4);
    const float4* src = (which == 0) ? Wq : (which == 1) ? Wk : Wv;
    float4 v = src[k * (Dn / 4) + seg];
    __half2* dst = (__half2*)&OutQKV[k * NQKV + (size_t)which * Dn + seg * 4];
    dst[0] = __floats2half2_rn(v.x, v.y);
    dst[1] = __floats2half2_rn(v.z, v.w);
}

// ============================================================================
// NT GEMM (fp32-acc, the validated roofline config from R14).
// EPI 0: WO -> fp32 out, single bias.  EPI 1: merged QKV -> fp16, per-slab
// bias/output selection, RoPE on q/k slabs.
// ============================================================================
#define NTBUF_B      (TILE_B + WTILE_B)   // 18944
#define GEMM_SMEM_NT (2 * NTBUF_B)        // 37888

template <int EPI>
__global__ void __launch_bounds__(256)
gemm_nt(const __half* __restrict__ A, const __half* __restrict__ W, int ldw,
        const float* __restrict__ b0, const float* __restrict__ b1,
        const float* __restrict__ b2,
        __half* __restrict__ o0, __half* __restrict__ o1,
        __half* __restrict__ o2, float* __restrict__ Cf)
{
    extern __shared__ char smem_raw[];
    const uint32_t sb = smem_u32(smem_raw);

    const int tid  = threadIdx.x;
    const int wid  = tid >> 5;
    const int lane = tid & 31;
    const int rowStart = blockIdx.y * 128;
    const int colStart = blockIdx.x * 128;
    const int which = colStart >> 11;
    const int ccol  = colStart & (Dn - 1);
    const int warp_m = (wid & 1) * 64;
    const int warp_n = (wid >> 1) * 32;

    const float* bias = (EPI == 0) ? b0 : (which == 0) ? b0 : (which == 1) ? b1 : b2;
    __half* OH = (which == 0) ? o0 : (which == 1) ? o1 : o2;
    const bool rope = (EPI == 1) && (which < 2);

    const __half* gA = A + (size_t)rowStart * Dn;
    const __half* gW = W + colStart;

    const uint32_t aoff  = (uint32_t)((lane & 15) * ROWB + (lane >> 4) * 16);
    const uint32_t boffT = (uint32_t)(((lane & 7) + ((lane >> 3) & 1) * 8) * VROWB
                                      + (lane >> 4) * 16);

    float acc[4][4][4];
    #pragma unroll
    for (int i = 0; i < 4; i++)
        #pragma unroll
        for (int j = 0; j < 4; j++)
            #pragma unroll
            for (int r = 0; r < 4; r++) acc[i][j][r] = 0.f;

    const int NCHUNK = Dn / KC;   // 64

    {
        const uint32_t bb = sb;
        load_tile (gA, Dn, bb, tid);
        load_wtile(gW, ldw, bb + TILE_B, tid);
        cp_commit();
    }

    #pragma unroll 1
    for (int c = 0; c < NCHUNK; ++c) {
        if (c + 1 < NCHUNK) {
            const uint32_t bb = sb + ((c + 1) & 1) * NTBUF_B;
            const int k0 = (c + 1) * KC;
            load_tile (gA + k0, Dn, bb, tid);
            load_wtile(gW + (size_t)k0 * ldw, ldw, bb + TILE_B, tid);
            cp_commit();
            cp_wait<1>();
        } else {
            cp_wait<0>();
        }
        __syncthreads();

        const uint32_t bb = sb + (c & 1) * NTBUF_B;
        const uint32_t sA = bb, sW = bb + TILE_B;

        #pragma unroll
        for (int kk = 0; kk < 2; ++kk) {
            const uint32_t kbA = (uint32_t)(kk * 32);
            const uint32_t kbB = (uint32_t)(kk * 16 * VROWB);
            uint32_t afrag[4][4], bfrag[4][2];

            #pragma unroll
            for (int i = 0; i < 4; ++i)
                ldsm4(afrag[i], sA + aoff + kbA + (uint32_t)((warp_m + i*16) * ROWB));
            #pragma unroll
            for (int g = 0; g < 2; ++g) {
                uint32_t r[4];
                ldsm4t(r, sW + boffT + kbB + (uint32_t)((warp_n + g*16) * 2));
                bfrag[g*2][0] = r[0]; bfrag[g*2][1] = r[1];
                bfrag[g*2+1][0] = r[2]; bfrag[g*2+1][1] = r[3];
            }
            #pragma unroll
            for (int i = 0; i < 4; ++i)
                #pragma unroll
                for (int j = 0; j < 4; ++j)
                    mma_f16(acc[i][j], afrag[i], bfrag[j]);
        }
        __syncthreads();
    }

    #pragma unroll
    for (int i = 0; i < 4; ++i) {
        const int r0 = rowStart + warp_m + i * 16 + (lane >> 2);
        #pragma unroll
        for (int half = 0; half < 2; ++half) {
            const int r = r0 + half * 8;
            const int s = r & (Sn - 1);
            #pragma unroll
            for (int j = 0; j < 4; ++j) {
                const int c0 = ccol + warp_n + j * 8 + (lane & 3) * 2;
                float v0 = acc[i][j][half*2]   + bias[c0];
                float v1 = acc[i][j][half*2+1] + bias[c0 + 1];
                if (rope) {
                    int pidx = (c0 & (HDn - 1)) >> 1;
                    float inv = exp2f((float)pidx * (-13.287712379549449f / 64.0f));
                    float sn, cs;
                    sincosf((float)s * inv, &sn, &cs);
                    float e = v0, o = v1;
                    v0 = e * cs - o * sn;
                    v1 = o * cs + e * sn;
                }
                if (EPI == 0)
                    *(float2*)&Cf[(size_t)r * Dn + c0] = make_float2(v0, v1);
                else
                    *(__half2*)&OH[(size_t)r * Dn + c0] = __floats2half2_rn(v0, v1);
            }
        }
    }
}

// ============================================================================
// Flash-fused attention (unchanged from R13/R14)
// ============================================================================
#define QSZ        (128 * VROWB)
#define KVSZ       (2 * QSZ)
#define FLASH_SMEM (QSZ + 2 * KVSZ)        // 174080

__global__ void __launch_bounds__(256)
flash_f16(const __half* __restrict__ Q, const __half* __restrict__ K,
          const __half* __restrict__ V, __half* __restrict__ O16)
{
    extern __shared__ char smem_raw[];
    const uint32_t sb = smem_u32(smem_raw);

    const int rb = blockIdx.x;
    const int bh = blockIdx.y;
    const int b  = bh >> 4, h = bh & 15;
    const int tid  = threadIdx.x;
    const int wid  = tid >> 5;
    const int lane = tid & 31;

    const size_t headoff = (size_t)(b * Sn) * Dn + h * HDn;
    const __half* gQ = Q + headoff + (size_t)(rb * 128) * Dn;
    const __half* gK = K + headoff;
    const __half* gV = V + headoff;

    const uint32_t sQ = sb;
    const uint32_t aoffV  = (uint32_t)((lane & 15) * VROWB + (lane >> 4) * 16);
    const uint32_t boffV  = (uint32_t)(((lane & 7) + ((lane >> 4) << 3)) * VROWB
                                       + ((lane >> 3) & 1) * 16);
    const uint32_t boffTV = (uint32_t)(((lane & 7) + ((lane >> 3) & 1) * 8) * VROWB
                                       + (lane >> 4) * 16);

    float oacc[16][4];
    #pragma unroll
    for (int j = 0; j < 16; ++j)
        #pragma unroll
        for (int r = 0; r < 4; ++r) oacc[j][r] = 0.f;
    float m[2] = {-1e30f, -1e30f};
    float l[2] = {0.f, 0.f};

    load_tile128w(gQ, sQ, tid);
    load_tile128w(gK, sb + QSZ, tid);
    load_tile128w(gV, sb + QSZ + QSZ, tid);
    cp_commit();

    const float scale = 0.08838834764831843f;
    const uint32_t aQ = sQ + (uint32_t)(wid * 16) * VROWB + aoffV;

    #pragma unroll 1
    for (int kb = 0; kb <= rb; ++kb) {
        if (kb < rb) {
            const uint32_t bb = sb + QSZ + ((kb + 1) & 1) * KVSZ;
            load_tile128w(gK + (size_t)((kb + 1) * 128) * Dn, bb, tid);
            load_tile128w(gV + (size_t)((kb + 1) * 128) * Dn, bb + QSZ, tid);
            cp_commit();
            cp_wait<1>();
        } else {
            cp_wait<0>();
        }
        __syncthreads();

        const uint32_t kvb = sb + QSZ + (kb & 1) * KVSZ;
        const uint32_t sK = kvb, sV = kvb + QSZ;

        float sacc[16][4];
        #pragma unroll
        for (int j = 0; j < 16; ++j)
            #pragma unroll
            for (int r = 0; r < 4; ++r) sacc[j][r] = 0.f;

        #pragma unroll
        for (int kd = 0; kd < 8; ++kd) {
            uint32_t af[4];
            ldsm4(af, aQ + (uint32_t)(kd * 32));
            #pragma unroll
            for (int p = 0; p < 8; ++p) {
                uint32_t r[4];
                ldsm4(r, sK + (uint32_t)(p * 16) * VROWB + boffV + (uint32_t)(kd * 32));
                uint32_t b0[2] = {r[0], r[1]}, b1[2] = {r[2], r[3]};
                mma_f16(sacc[2*p],     af, b0);
                mma_f16(sacc[2*p + 1], af, b1);
            }
        }

        const bool diag = (kb == rb);
        #pragma unroll
        for (int j = 0; j < 16; ++j)
            #pragma unroll
            for (int r = 0; r < 4; ++r) {
                float v = sacc[j][r] * scale;
                if (diag) {
                    int t_loc = j * 8 + (lane & 3) * 2 + (r & 1);
                    int s_loc = wid * 16 + (lane >> 2) + ((r >> 1) & 1) * 8;
                    if (t_loc > s_loc) v = -1e30f;
                }
                sacc[j][r] = v;
            }

        float bm[2] = {-1e30f, -1e30f};
        #pragma unroll
        for (int j = 0; j < 16; ++j) {
            bm[0] = fmaxf(bm[0], fmaxf(sacc[j][0], sacc[j][1]));
            bm[1] = fmaxf(bm[1], fmaxf(sacc[j][2], sacc[j][3]));
        }
        #pragma unroll
        for (int o = 1; o <= 2; o <<= 1) {
            bm[0] = fmaxf(bm[0], __shfl_xor_sync(0xffffffffu, bm[0], o));
            bm[1] = fmaxf(bm[1], __shfl_xor_sync(0xffffffffu, bm[1], o));
        }
        float mn[2], f[2];
        #pragma unroll
        for (int hh = 0; hh < 2; ++hh) {
            mn[hh] = fmaxf(m[hh], bm[hh]);
            f[hh]  = __expf(m[hh] - mn[hh]);
            m[hh]  = mn[hh];
        }

        float rs[2] = {0.f, 0.f};
        #pragma unroll
        for (int j = 0; j < 16; ++j) {
            #pragma unroll
            for (int r = 0; r < 4; ++r) {
                const int hh = r >> 1;
                float e = __expf(sacc[j][r] - mn[hh]);
                sacc[j][r] = e;
                rs[hh] += e;
            }
        }
        #pragma unroll
        for (int o = 1; o <= 2; o <<= 1) {
            rs[0] += __shfl_xor_sync(0xffffffffu, rs[0], o);
            rs[1] += __shfl_xor_sync(0xffffffffu, rs[1], o);
        }
        l[0] = l[0] * f[0] + rs[0];
        l[1] = l[1] * f[1] + rs[1];

        #pragma unroll
        for (int j = 0; j < 16; ++j) {
            oacc[j][0] *= f[0]; oacc[j][1] *= f[0];
            oacc[j][2] *= f[1]; oacc[j][3] *= f[1];
        }

        #pragma unroll
        for (int kt = 0; kt < 8; ++kt) {
            uint32_t pk[4];
            pk[0] = pack_h2(sacc[2*kt][0],     sacc[2*kt][1]);
            pk[1] = pack_h2(sacc[2*kt][2],     sacc[2*kt][3]);
            pk[2] = pack_h2(sacc[2*kt + 1][0], sacc[2*kt + 1][1]);
            pk[3] = pack_h2(sacc[2*kt + 1][2], sacc[2*kt + 1][3]);
            #pragma unroll
            for (int g = 0; g < 8; ++g) {
                uint32_t r[4];
                ldsm4t(r, sV + (uint32_t)(kt * 16) * VROWB + boffTV + (uint32_t)(g * 32));
                uint32_t b0[2] = {r[0], r[1]}, b1[2] = {r[2], r[3]};
                mma_f16(oacc[2*g],     pk, b0);
                mma_f16(oacc[2*g + 1], pk, b1);
            }
        }
        __syncthreads();
    }

    const float inv0 = 1.f / l[0], inv1 = 1.f / l[1];
    #pragma unroll
    for (int hh = 0; hh < 2; ++hh) {
        const int s = rb * 128 + wid * 16 + (lane >> 2) + hh * 8;
        const size_t rbase = ((size_t)(b * Sn + s)) * Dn + h * HDn;
        const float inv = hh ? inv1 : inv0;
        #pragma unroll
        for (int j = 0; j < 16; ++j) {
            const int d = j * 8 + (lane & 3) * 2;
            *(__half2*)&O16[rbase + d] =
                __floats2half2_rn(oacc[j][hh*2] * inv, oacc[j][hh*2 + 1] * inv);
        }
    }
}

// ============================================================================
extern "C" void kernel_launch(void* const* d_in, const int* in_sizes, int n_in,
                              void* d_out, int out_size)
{
    const float* x  = (const float*)d_in[0];
    const float* wq = (const float*)d_in[2];
    const float* bq = (const float*)d_in[3];
    const float* wk = (const float*)d_in[4];
    const float* bk = (const float*)d_in[5];
    const float* wv = (const float*)d_in[6];
    const float* bv = (const float*)d_in[7];
    const float* wo = (const float*)d_in[8];
    const float* bo = (const float*)d_in[9];
    float* out = (float*)d_out;

    __half *x16, *o16, *wqkv, *wo16, *q16, *k16, *v16;
    cudaGetSymbolAddress((void**)&x16,  g_x16);
    cudaGetSymbolAddress((void**)&o16,  g_o16);
    cudaGetSymbolAddress((void**)&wqkv, g_wqkv);
    cudaGetSymbolAddress((void**)&wo16, g_wo16);
    cudaGetSymbolAddress((void**)&q16,  g_q16);
    cudaGetSymbolAddress((void**)&k16,  g_k16);
    cudaGetSymbolAddress((void**)&v16,  g_v16);

    cudaFuncSetAttribute(gemm_nt<0>, cudaFuncAttributeMaxDynamicSharedMemorySize, GEMM_SMEM_NT);
    cudaFuncSetAttribute(gemm_nt<1>, cudaFuncAttributeMaxDynamicSharedMemorySize, GEMM_SMEM_NT);
    cudaFuncSetAttribute(flash_f16,  cudaFuncAttributeMaxDynamicSharedMemorySize, FLASH_SMEM);

    const int nXBlks  = (int)(((size_t)Mtot * Dn / 4) / 256);        // 16384
    const int nW4Blks = (int)(((size_t)4 * Dn * Dn / 4) / 256);      // 16384

    // --- preprocessing (2 launches) ---
    half_kernel<<<nXBlks, 256>>>((const float4*)x, x16);
    convW4_kernel<<<nW4Blks, 256>>>((const float4*)wq, (const float4*)wk,
                                    (const float4*)wv, (const float4*)wo,
                                    wqkv, wo16);

    // --- merged QKV projection (fp32-acc, validated roofline) ---
    dim3 gQKV(NQKV / 128, Mtot / 128);
    gemm_nt<1><<<gQKV, 256, GEMM_SMEM_NT>>>(x16, wqkv, NQKV,
                                            bq, bk, bv, q16, k16, v16, nullptr);

    // --- flash-fused attention ---
    dim3 gF(Sn / 128, Bn * Hn);
    flash_f16<<<gF, 256, FLASH_SMEM>>>(q16, k16, v16, o16);

    // --- output projection (fp32-acc) ---
    dim3 gWO(Dn / 128, Mtot / 128);
    gemm_nt<0><<<gWO, 256, GEMM_SMEM_NT>>>(o16, wo16, Dn,
                                           bo, nullptr, nullptr,
                                           nullptr, nullptr, nullptr, out);
}

// round 17
// speedup vs baseline: 1.4701x; 1.0031x over previous
#include <cuda_runtime.h>
#include <cuda_fp16.h>
#include <math.h>
#include <stdint.h>

#define Bn   16
#define Sn   512
#define Dn   2048
#define Hn   16
#define HDn  128
#define Mtot (Bn*Sn)      // 8192
#define NQKV (3 * Dn)     // 6144

// ---------------- scratch (alloc-free: __device__ globals) ----------------
__device__ __half g_x16[(size_t)Mtot * Dn];
__device__ __half g_o16[(size_t)Mtot * Dn];
__device__ __half g_wqkv[(size_t)Dn * NQKV];   // [k][n'] n'=6144
__device__ __half g_wo16[(size_t)Dn * Dn];     // [k][n]
__device__ __half g_q16[(size_t)Mtot * Dn];
__device__ __half g_k16[(size_t)Mtot * Dn];
__device__ __half g_v16[(size_t)Mtot * Dn];

// ============================================================================
// PTX helpers
// ============================================================================
__device__ __forceinline__ uint32_t smem_u32(const void* p) {
    uint32_t a;
    asm("{ .reg .u64 t; cvta.to.shared.u64 t, %1; cvt.u32.u64 %0, t; }" : "=r"(a) : "l"(p));
    return a;
}
__device__ __forceinline__ void cp16(uint32_t saddr, const void* gptr) {
    asm volatile("cp.async.cg.shared.global [%0], [%1], 16;" :: "r"(saddr), "l"(gptr) : "memory");
}
__device__ __forceinline__ void cp_commit() {
    asm volatile("cp.async.commit_group;" ::: "memory");
}
template <int N>
__device__ __forceinline__ void cp_wait() {
    asm volatile("cp.async.wait_group %0;" :: "n"(N) : "memory");
}
__device__ __forceinline__ void ldsm4(uint32_t* r, uint32_t addr) {
    asm volatile("ldmatrix.sync.aligned.m8n8.x4.shared.b16 {%0,%1,%2,%3}, [%4];"
                 : "=r"(r[0]), "=r"(r[1]), "=r"(r[2]), "=r"(r[3]) : "r"(addr));
}
__device__ __forceinline__ void ldsm4t(uint32_t* r, uint32_t addr) {
    asm volatile("ldmatrix.sync.aligned.m8n8.x4.trans.shared.b16 {%0,%1,%2,%3}, [%4];"
                 : "=r"(r[0]), "=r"(r[1]), "=r"(r[2]), "=r"(r[3]) : "r"(addr));
}
__device__ __forceinline__ void mma_f16(float* d, const uint32_t* a, const uint32_t* b) {
    asm volatile("mma.sync.aligned.m16n8k16.row.col.f32.f16.f16.f32 "
                 "{%0,%1,%2,%3}, {%4,%5,%6,%7}, {%8,%9}, {%0,%1,%2,%3};"
                 : "+f"(d[0]), "+f"(d[1]), "+f"(d[2]), "+f"(d[3])
                 : "r"(a[0]), "r"(a[1]), "r"(a[2]), "r"(a[3]), "r"(b[0]), "r"(b[1]));
}
__device__ __forceinline__ uint32_t pack_h2(float a, float b) {
    __half2 h = __floats2half2_rn(a, b);
    return *reinterpret_cast<uint32_t*>(&h);
}

// ============================================================================
// Tile geometry
// ============================================================================
#define KC      32
#define ROWB    80
#define TILE_B  (128 * ROWB)         // 10240 B
#define VROWB   272
#define WTILE_B (32 * VROWB)         // 8704 B

template <typename T>
__device__ __forceinline__ void load_tile(const T* __restrict__ g,
                                          int ldg, uint32_t sdst, int tid)
{
    #pragma unroll
    for (int it = 0; it < 2; ++it) {
        int idx = tid + it * 256;
        int row = idx >> 2, seg = idx & 3;
        cp16(sdst + (uint32_t)(row * ROWB + seg * 16),
             (const char*)(g + (size_t)row * ldg) + seg * 16);
    }
}
__device__ __forceinline__ void load_wtile(const __half* __restrict__ g,
                                           int ldg, uint32_t sdst, int tid)
{
    #pragma unroll
    for (int it = 0; it < 2; ++it) {
        int idx = tid + it * 256;
        int row = idx >> 4, seg = idx & 15;
        cp16(sdst + (uint32_t)(row * VROWB + seg * 16),
             (const char*)(g + (size_t)row * ldg) + seg * 16);
    }
}
__device__ __forceinline__ void load_tile128w(const __half* __restrict__ g,
                                              uint32_t sdst, int tid)
{
    #pragma unroll
    for (int it = 0; it < 8; ++it) {
        int idx = tid + it * 256;
        int row = idx >> 4, seg = idx & 15;
        cp16(sdst + (uint32_t)(row * VROWB + seg * 16),
             (const char*)(g + (size_t)row * Dn) + seg * 16);
    }
}

// ============================================================================
// Preprocessing: x AND all 4 W matrices converted in ONE launch.
// Blocks [0, nX) convert x; blocks [nX, nX+4*QW) convert weights.
// ============================================================================
__global__ void __launch_bounds__(256)
conv_all_kernel(const float4* __restrict__ X,
                const float4* __restrict__ Wq, const float4* __restrict__ Wk,
                const float4* __restrict__ Wv, const float4* __restrict__ Wo,
                __half* __restrict__ X16,
                __half* __restrict__ OutQKV, __half* __restrict__ OutO,
                int nXBlks)
{
    const size_t QUARTER = (size_t)Dn * Dn / 4;    // float4 per weight matrix

    if (blockIdx.x < (unsigned)nXBlks) {
        size_t i = (size_t)blockIdx.x * 256 + threadIdx.x;
        float4 v = X[i];
        __half2* H2 = (__half2*)X16;
        H2[2*i]   = __floats2half2_rn(v.x, v.y);
        H2[2*i+1] = __floats2half2_rn(v.z, v.w);
        return;
    }

    size_t idx = (size_t)(blockIdx.x - nXBlks) * 256 + threadIdx.x;
    int which = (int)(idx / QUARTER);
    size_t rem = idx - (size_t)which * QUARTER;

    if (which == 3) {
        float4 v = Wo[rem];
        __half2* dst = (__half2*)&OutO[rem * 4];
        dst[0] = __floats2half2_rn(v.x, v.y);
        dst[1] = __floats2half2_rn(v.z, v.w);
        return;
    }
    size_t k   = rem / (Dn / 4);
    size_t seg = rem - k * (Dn / 4);
    const float4* src = (which == 0) ? Wq : (which == 1) ? Wk : Wv;
    float4 v = src[k * (Dn / 4) + seg];
    __half2* dst = (__half2*)&OutQKV[k * NQKV + (size_t)which * Dn + seg * 4];
    dst[0] = __floats2half2_rn(v.x, v.y);
    dst[1] = __floats2half2_rn(v.z, v.w);
}

// ============================================================================
// NT GEMM (fp32-acc, validated roofline config).
// EPI 0: WO -> fp32 out, single bias.  EPI 1: merged QKV -> fp16, per-slab
// bias/output selection, RoPE on q/k slabs.
// ============================================================================
#define NTBUF_B      (TILE_B + WTILE_B)   // 18944
#define GEMM_SMEM_NT (2 * NTBUF_B)        // 37888

template <int EPI>
__global__ void __launch_bounds__(256)
gemm_nt(const __half* __restrict__ A, const __half* __restrict__ W, int ldw,
        const float* __restrict__ b0, const float* __restrict__ b1,
        const float* __restrict__ b2,
        __half* __restrict__ o0, __half* __restrict__ o1,
        __half* __restrict__ o2, float* __restrict__ Cf)
{
    extern __shared__ char smem_raw[];
    const uint32_t sb = smem_u32(smem_raw);

    const int tid  = threadIdx.x;
    const int wid  = tid >> 5;
    const int lane = tid & 31;
    const int rowStart = blockIdx.y * 128;
    const int colStart = blockIdx.x * 128;
    const int which = colStart >> 11;
    const int ccol  = colStart & (Dn - 1);
    const int warp_m = (wid & 1) * 64;
    const int warp_n = (wid >> 1) * 32;

    const float* bias = (EPI == 0) ? b0 : (which == 0) ? b0 : (which == 1) ? b1 : b2;
    __half* OH = (which == 0) ? o0 : (which == 1) ? o1 : o2;
    const bool rope = (EPI == 1) && (which < 2);

    const __half* gA = A + (size_t)rowStart * Dn;
    const __half* gW = W + colStart;

    const uint32_t aoff  = (uint32_t)((lane & 15) * ROWB + (lane >> 4) * 16);
    const uint32_t boffT = (uint32_t)(((lane & 7) + ((lane >> 3) & 1) * 8) * VROWB
                                      + (lane >> 4) * 16);

    float acc[4][4][4];
    #pragma unroll
    for (int i = 0; i < 4; i++)
        #pragma unroll
        for (int j = 0; j < 4; j++)
            #pragma unroll
            for (int r = 0; r < 4; r++) acc[i][j][r] = 0.f;

    const int NCHUNK = Dn / KC;   // 64

    {
        const uint32_t bb = sb;
        load_tile (gA, Dn, bb, tid);
        load_wtile(gW, ldw, bb + TILE_B, tid);
        cp_commit();
    }

    #pragma unroll 1
    for (int c = 0; c < NCHUNK; ++c) {
        if (c + 1 < NCHUNK) {
            const uint32_t bb = sb + ((c + 1) & 1) * NTBUF_B;
            const int k0 = (c + 1) * KC;
            load_tile (gA + k0, Dn, bb, tid);
            load_wtile(gW + (size_t)k0 * ldw, ldw, bb + TILE_B, tid);
            cp_commit();
            cp_wait<1>();
        } else {
            cp_wait<0>();
        }
        __syncthreads();

        const uint32_t bb = sb + (c & 1) * NTBUF_B;
        const uint32_t sA = bb, sW = bb + TILE_B;

        #pragma unroll
        for (int kk = 0; kk < 2; ++kk) {
            const uint32_t kbA = (uint32_t)(kk * 32);
            const uint32_t kbB = (uint32_t)(kk * 16 * VROWB);
            uint32_t afrag[4][4], bfrag[4][2];

            #pragma unroll
            for (int i = 0; i < 4; ++i)
                ldsm4(afrag[i], sA + aoff + kbA + (uint32_t)((warp_m + i*16) * ROWB));
            #pragma unroll
            for (int g = 0; g < 2; ++g) {
                uint32_t r[4];
                ldsm4t(r, sW + boffT + kbB + (uint32_t)((warp_n + g*16) * 2));
                bfrag[g*2][0] = r[0]; bfrag[g*2][1] = r[1];
                bfrag[g*2+1][0] = r[2]; bfrag[g*2+1][1] = r[3];
            }
            #pragma unroll
            for (int i = 0; i < 4; ++i)
                #pragma unroll
                for (int j = 0; j < 4; ++j)
                    mma_f16(acc[i][j], afrag[i], bfrag[j]);
        }
        __syncthreads();
    }

    #pragma unroll
    for (int i = 0; i < 4; ++i) {
        const int r0 = rowStart + warp_m + i * 16 + (lane >> 2);
        #pragma unroll
        for (int half = 0; half < 2; ++half) {
            const int r = r0 + half * 8;
            const int s = r & (Sn - 1);
            #pragma unroll
            for (int j = 0; j < 4; ++j) {
                const int c0 = ccol + warp_n + j * 8 + (lane & 3) * 2;
                float v0 = acc[i][j][half*2]   + bias[c0];
                float v1 = acc[i][j][half*2+1] + bias[c0 + 1];
                if (rope) {
                    int pidx = (c0 & (HDn - 1)) >> 1;
                    float inv = exp2f((float)pidx * (-13.287712379549449f / 64.0f));
                    float sn, cs;
                    sincosf((float)s * inv, &sn, &cs);
                    float e = v0, o = v1;
                    v0 = e * cs - o * sn;
                    v1 = o * cs + e * sn;
                }
                if (EPI == 0)
                    *(float2*)&Cf[(size_t)r * Dn + c0] = make_float2(v0, v1);
                else
                    *(__half2*)&OH[(size_t)r * Dn + c0] = __floats2half2_rn(v0, v1);
            }
        }
    }
}

// ============================================================================
// Flash-fused attention. Heavy-first scheduling: rb = 3 - blockIdx.x so
// 4-step CTAs launch in wave 1 and 1-step CTAs fill the tail.
// ============================================================================
#define QSZ        (128 * VROWB)
#define KVSZ       (2 * QSZ)
#define FLASH_SMEM (QSZ + 2 * KVSZ)        // 174080

__global__ void __launch_bounds__(256)
flash_f16(const __half* __restrict__ Q, const __half* __restrict__ K,
          const __half* __restrict__ V, __half* __restrict__ O16)
{
    extern __shared__ char smem_raw[];
    const uint32_t sb = smem_u32(smem_raw);

    const int rb = (Sn / 128 - 1) - blockIdx.x;   // heavy blocks first
    const int bh = blockIdx.y;
    const int b  = bh >> 4, h = bh & 15;
    const int tid  = threadIdx.x;
    const int wid  = tid >> 5;
    const int lane = tid & 31;

    const size_t headoff = (size_t)(b * Sn) * Dn + h * HDn;
    const __half* gQ = Q + headoff + (size_t)(rb * 128) * Dn;
    const __half* gK = K + headoff;
    const __half* gV = V + headoff;

    const uint32_t sQ = sb;
    const uint32_t aoffV  = (uint32_t)((lane & 15) * VROWB + (lane >> 4) * 16);
    const uint32_t boffV  = (uint32_t)(((lane & 7) + ((lane >> 4) << 3)) * VROWB
                                       + ((lane >> 3) & 1) * 16);
    const uint32_t boffTV = (uint32_t)(((lane & 7) + ((lane >> 3) & 1) * 8) * VROWB
                                       + (lane >> 4) * 16);

    float oacc[16][4];
    #pragma unroll
    for (int j = 0; j < 16; ++j)
        #pragma unroll
        for (int r = 0; r < 4; ++r) oacc[j][r] = 0.f;
    float m[2] = {-1e30f, -1e30f};
    float l[2] = {0.f, 0.f};

    load_tile128w(gQ, sQ, tid);
    load_tile128w(gK, sb + QSZ, tid);
    load_tile128w(gV, sb + QSZ + QSZ, tid);
    cp_commit();

    const float scale = 0.08838834764831843f;
    const uint32_t aQ = sQ + (uint32_t)(wid * 16) * VROWB + aoffV;

    #pragma unroll 1
    for (int kb = 0; kb <= rb; ++kb) {
        if (kb < rb) {
            const uint32_t bb = sb + QSZ + ((kb + 1) & 1) * KVSZ;
            load_tile128w(gK + (size_t)((kb + 1) * 128) * Dn, bb, tid);
            load_tile128w(gV + (size_t)((kb + 1) * 128) * Dn, bb + QSZ, tid);
            cp_commit();
            cp_wait<1>();
        } else {
            cp_wait<0>();
        }
        __syncthreads();

        const uint32_t kvb = sb + QSZ + (kb & 1) * KVSZ;
        const uint32_t sK = kvb, sV = kvb + QSZ;

        float sacc[16][4];
        #pragma unroll
        for (int j = 0; j < 16; ++j)
            #pragma unroll
            for (int r = 0; r < 4; ++r) sacc[j][r] = 0.f;

        #pragma unroll
        for (int kd = 0; kd < 8; ++kd) {
            uint32_t af[4];
            ldsm4(af, aQ + (uint32_t)(kd * 32));
            #pragma unroll
            for (int p = 0; p < 8; ++p) {
                uint32_t r[4];
                ldsm4(r, sK + (uint32_t)(p * 16) * VROWB + boffV + (uint32_t)(kd * 32));
                uint32_t b0[2] = {r[0], r[1]}, b1[2] = {r[2], r[3]};
                mma_f16(sacc[2*p],     af, b0);
                mma_f16(sacc[2*p + 1], af, b1);
            }
        }

        const bool diag = (kb == rb);
        #pragma unroll
        for (int j = 0; j < 16; ++j)
            #pragma unroll
            for (int r = 0; r < 4; ++r) {
                float v = sacc[j][r] * scale;
                if (diag) {
                    int t_loc = j * 8 + (lane & 3) * 2 + (r & 1);
                    int s_loc = wid * 16 + (lane >> 2) + ((r >> 1) & 1) * 8;
                    if (t_loc > s_loc) v = -1e30f;
                }
                sacc[j][r] = v;
            }

        float bm[2] = {-1e30f, -1e30f};
        #pragma unroll
        for (int j = 0; j < 16; ++j) {
            bm[0] = fmaxf(bm[0], fmaxf(sacc[j][0], sacc[j][1]));
            bm[1] = fmaxf(bm[1], fmaxf(sacc[j][2], sacc[j][3]));
        }
        #pragma unroll
        for (int o = 1; o <= 2; o <<= 1) {
            bm[0] = fmaxf(bm[0], __shfl_xor_sync(0xffffffffu, bm[0], o));
            bm[1] = fmaxf(bm[1], __shfl_xor_sync(0xffffffffu, bm[1], o));
        }
        float mn[2], f[2];
        #pragma unroll
        for (int hh = 0; hh < 2; ++hh) {
            mn[hh] = fmaxf(m[hh], bm[hh]);
            f[hh]  = __expf(m[hh] - mn[hh]);
            m[hh]  = mn[hh];
        }

        float rs[2] = {0.f, 0.f};
        #pragma unroll
        for (int j = 0; j < 16; ++j) {
            #pragma unroll
            for (int r = 0; r < 4; ++r) {
                const int hh = r >> 1;
                float e = __expf(sacc[j][r] - mn[hh]);
                sacc[j][r] = e;
                rs[hh] += e;
            }
        }
        #pragma unroll
        for (int o = 1; o <= 2; o <<= 1) {
            rs[0] += __shfl_xor_sync(0xffffffffu, rs[0], o);
            rs[1] += __shfl_xor_sync(0xffffffffu, rs[1], o);
        }
        l[0] = l[0] * f[0] + rs[0];
        l[1] = l[1] * f[1] + rs[1];

        #pragma unroll
        for (int j = 0; j < 16; ++j) {
            oacc[j][0] *= f[0]; oacc[j][1] *= f[0];
            oacc[j][2] *= f[1]; oacc[j][3] *= f[1];
        }

        #pragma unroll
        for (int kt = 0; kt < 8; ++kt) {
            uint32_t pk[4];
            pk[0] = pack_h2(sacc[2*kt][0],     sacc[2*kt][1]);
            pk[1] = pack_h2(sacc[2*kt][2],     sacc[2*kt][3]);
            pk[2] = pack_h2(sacc[2*kt + 1][0], sacc[2*kt + 1][1]);
            pk[3] = pack_h2(sacc[2*kt + 1][2], sacc[2*kt + 1][3]);
            #pragma unroll
            for (int g = 0; g < 8; ++g) {
                uint32_t r[4];
                ldsm4t(r, sV + (uint32_t)(kt * 16) * VROWB + boffTV + (uint32_t)(g * 32));
                uint32_t b0[2] = {r[0], r[1]}, b1[2] = {r[2], r[3]};
                mma_f16(oacc[2*g],     pk, b0);
                mma_f16(oacc[2*g + 1], pk, b1);
            }
        }
        __syncthreads();
    }

    const float inv0 = 1.f / l[0], inv1 = 1.f / l[1];
    #pragma unroll
    for (int hh = 0; hh < 2; ++hh) {
        const int s = rb * 128 + wid * 16 + (lane >> 2) + hh * 8;
        const size_t rbase = ((size_t)(b * Sn + s)) * Dn + h * HDn;
        const float inv = hh ? inv1 : inv0;
        #pragma unroll
        for (int j = 0; j < 16; ++j) {
            const int d = j * 8 + (lane & 3) * 2;
            *(__half2*)&O16[rbase + d] =
                __floats2half2_rn(oacc[j][hh*2] * inv, oacc[j][hh*2 + 1] * inv);
        }
    }
}

// ============================================================================
extern "C" void kernel_launch(void* const* d_in, const int* in_sizes, int n_in,
                              void* d_out, int out_size)
{
    const float* x  = (const float*)d_in[0];
    const float* wq = (const float*)d_in[2];
    const float* bq = (const float*)d_in[3];
    const float* wk = (const float*)d_in[4];
    const float* bk = (const float*)d_in[5];
    const float* wv = (const float*)d_in[6];
    const float* bv = (const float*)d_in[7];
    const float* wo = (const float*)d_in[8];
    const float* bo = (const float*)d_in[9];
    float* out = (float*)d_out;

    __half *x16, *o16, *wqkv, *wo16, *q16, *k16, *v16;
    cudaGetSymbolAddress((void**)&x16,  g_x16);
    cudaGetSymbolAddress((void**)&o16,  g_o16);
    cudaGetSymbolAddress((void**)&wqkv, g_wqkv);
    cudaGetSymbolAddress((void**)&wo16, g_wo16);
    cudaGetSymbolAddress((void**)&q16,  g_q16);
    cudaGetSymbolAddress((void**)&k16,  g_k16);
    cudaGetSymbolAddress((void**)&v16,  g_v16);

    cudaFuncSetAttribute(gemm_nt<0>, cudaFuncAttributeMaxDynamicSharedMemorySize, GEMM_SMEM_NT);
    cudaFuncSetAttribute(gemm_nt<1>, cudaFuncAttributeMaxDynamicSharedMemorySize, GEMM_SMEM_NT);
    cudaFuncSetAttribute(flash_f16,  cudaFuncAttributeMaxDynamicSharedMemorySize, FLASH_SMEM);

    const int nXBlks  = (int)(((size_t)Mtot * Dn / 4) / 256);        // 16384
    const int nW4Blks = (int)(((size_t)4 * Dn * Dn / 4) / 256);      // 16384

    // --- preprocessing (ONE launch: x + all 4 weight matrices) ---
    conv_all_kernel<<<nXBlks + nW4Blks, 256>>>(
        (const float4*)x, (const float4*)wq, (const float4*)wk,
        (const float4*)wv, (const float4*)wo, x16, wqkv, wo16, nXBlks);

    // --- merged QKV projection (fp32-acc, validated roofline) ---
    dim3 gQKV(NQKV / 128, Mtot / 128);
    gemm_nt<1><<<gQKV, 256, GEMM_SMEM_NT>>>(x16, wqkv, NQKV,
                                            bq, bk, bv, q16, k16, v16, nullptr);

    // --- flash-fused attention (heavy-first block order) ---
    dim3 gF(Sn / 128, Bn * Hn);
    flash_f16<<<gF, 256, FLASH_SMEM>>>(q16, k16, v16, o16);

    // --- output projection (fp32-acc) ---
    dim3 gWO(Dn / 128, Mtot / 128);
    gemm_nt<0><<<gWO, 256, GEMM_SMEM_NT>>>(o16, wo16, Dn,
                                           bo, nullptr, nullptr,
                                           nullptr, nullptr, nullptr, out);
}